// round 8
// baseline (speedup 1.0000x reference)
#include <cuda_runtime.h>

#define NQ   4
#define DIM  16
#define NH   8
#define NL   2
#define EMB  32
#define NT3  81   // 3^4 basis terms per head
#define BLK  128  // threads per block
#define TPT  2    // tokens per thread

typedef unsigned long long u64;

// ---- packed f32x2 helpers -------------------------------------------------
#define FMAX2(d, a, b, c) \
    asm("fma.rn.f32x2 %0, %1, %2, %3;" : "=l"(d) : "l"(a), "l"(b), "l"(c))
#define MUL2(d, a, b) \
    asm("mul.rn.f32x2 %0, %1, %2;" : "=l"(d) : "l"(a), "l"(b))
#define ADD2(d, a, b) \
    asm("add.rn.f32x2 %0, %1, %2;" : "=l"(d) : "l"(a), "l"(b))
#define PACK2(d, lo, hi) \
    asm("mov.b64 %0, {%1, %2};" : "=l"(d) : "f"(lo), "f"(hi))
#define UNPACK2(lo, hi, d) \
    asm("mov.b64 {%0, %1}, %2;" : "=f"(lo), "=f"(hi) : "l"(d))

// All warp-uniform tables live in ONE blob: computed into __device__ memory by
// the setup kernel, then memcpy'd (D2D, graph-capturable) into __constant__.
struct __align__(16) CBlob {
    ulonglong2 C[NH * NT3];   // [h][t]: packed ((c0,c1),(c2,c3))
    ulonglong2 Wq[NH * 32];   // [h][i][k]: ((W[4k],W[4k+1]),(W[4k+2],W[4k+3])) col 4h+i
    u64        b2[16];        // (b[2j], b[2j+1])
};
__device__   CBlob g_blob;
__constant__ CBlob c_blob;

// ---------------------------------------------------------------------------
// Setup kernel: shuffle-parallel simulation of the fixed per-head unitary.
// 8 blocks x 256 threads; thread (k,m) holds amplitude <m|U|k>.
// Block 0 additionally packs W and bias into the blob.
// ---------------------------------------------------------------------------
__global__ void qc_setup_kernel(const float* __restrict__ params,
                                const float* __restrict__ W,
                                const float* __restrict__ bias) {
    __shared__ float Vre[DIM][DIM + 1];
    __shared__ float Vim[DIM][DIM + 1];
    __shared__ float Msh[DIM * DIM][4];

    const int h   = blockIdx.x;
    const int tid = threadIdx.x;     // 0..255
    const int m   = tid & 15;        // amplitude index
    const int k   = tid >> 4;        // input basis state

    // Block 0: pack W (fold layout) and bias.
    if (h == 0) {
        const int kk = tid & 7;
        const int c  = tid >> 3;     // c = 4h + i_ev in [0,32)
        u64 lo, hi;
        PACK2(lo, W[(4 * kk + 0) * EMB + c], W[(4 * kk + 1) * EMB + c]);
        PACK2(hi, W[(4 * kk + 2) * EMB + c], W[(4 * kk + 3) * EMB + c]);
        g_blob.Wq[tid] = make_ulonglong2(lo, hi);
        if (tid < 16) {
            u64 v;
            PACK2(v, bias[2 * tid], bias[2 * tid + 1]);
            g_blob.b2[tid] = v;
        }
    }

    float re = (k == m) ? 1.f : 0.f;
    float im = 0.f;

    const float* p = params + h * NL * NQ * 3;

    #pragma unroll
    for (int l = 0; l < NL; l++) {
        #pragma unroll
        for (int q = 0; q < NQ; q++) {
            const int mask = 8 >> q;   // qubit 0 = MSB
            float th, c, s, r1, i1;

            // RX
            th = p[(l * NQ + q) * 3 + 0];
            c = cosf(0.5f * th); s = sinf(0.5f * th);
            r1 = __shfl_xor_sync(0xffffffffu, re, mask);
            i1 = __shfl_xor_sync(0xffffffffu, im, mask);
            re = c * re + s * i1;
            im = c * im - s * r1;

            // RY
            th = p[(l * NQ + q) * 3 + 1];
            c = cosf(0.5f * th); s = sinf(0.5f * th);
            r1 = __shfl_xor_sync(0xffffffffu, re, mask);
            i1 = __shfl_xor_sync(0xffffffffu, im, mask);
            {
                const float sgn = (m & mask) ? s : -s;
                re = c * re + sgn * r1;
                im = c * im + sgn * i1;
            }

            // RZ
            th = p[(l * NQ + q) * 3 + 2];
            c = cosf(0.5f * th); s = sinf(0.5f * th);
            {
                const float sg = (m & mask) ? s : -s;
                const float r = re, i = im;
                re = c * r - sg * i;
                im = c * i + sg * r;
            }
        }
        // CNOT chain
        const int cm[4] = {8, 4, 2, 1};
        const int tm[4] = {4, 2, 1, 8};
        #pragma unroll
        for (int e = 0; e < 4; e++) {
            const float r1 = __shfl_xor_sync(0xffffffffu, re, tm[e]);
            const float i1 = __shfl_xor_sync(0xffffffffu, im, tm[e]);
            if (m & cm[e]) { re = r1; im = i1; }
        }
    }

    Vre[k][m] = re;
    Vim[k][m] = im;
    __syncthreads();

    // M_i[k,l] = sum_m z_i(m) Re(conj(V[m,k]) V[m,l])
    {
        const int kk = tid >> 4;
        const int ll = tid & 15;
        float P[DIM];
        float tot = 0.f;
        #pragma unroll
        for (int mm = 0; mm < DIM; mm++) {
            P[mm] = Vre[kk][mm] * Vre[ll][mm] + Vim[kk][mm] * Vim[ll][mm];
            tot += P[mm];
        }
        #pragma unroll
        for (int i = 0; i < 4; i++) {
            float sub = 0.f;
            #pragma unroll
            for (int mm = 0; mm < DIM; mm++)
                if ((mm >> (3 - i)) & 1) sub += P[mm];
            Msh[tid][i] = tot - 2.f * sub;
        }
    }
    __syncthreads();

    // Expand into the 81-term basis via Msh lookups.
    for (int idx = tid; idx < 4 * NT3; idx += blockDim.x) {
        const int i = idx / NT3;
        const int t = idx % NT3;
        const int tq[4] = { t / 27, (t / 9) % 3, (t / 3) % 3, t % 3 };

        float acc = 0.f;
        for (int b = 0; b < 16; b++) {
            int kk = 0, ll = 0;
            float sgn = 1.f / 16.f;
            #pragma unroll
            for (int q = 0; q < 4; q++) {
                const int bq = (b >> q) & 1;
                const int sh = 3 - q;
                if (tq[q] == 2) {
                    kk |= bq << sh; ll |= (1 - bq) << sh;
                } else {
                    kk |= bq << sh; ll |= bq << sh;
                    if (tq[q] == 1 && bq) sgn = -sgn;
                }
            }
            acc += sgn * Msh[kk * DIM + ll][i];
        }
        ((float*)g_blob.C)[(h * NT3 + t) * 4 + i] = acc;
    }
}

// ---------------------------------------------------------------------------
// Main kernel: 2 tokens/thread, f32x2 packed over ev-index pairs.
// Tables from __constant__ (uniform LDC). ev accumulators are split 3-ways
// by a-branch -> 12 independent FMA chains; __launch_bounds__(128,3) gives
// ptxas a 170-reg budget to keep many LDC.128s in flight.
// ---------------------------------------------------------------------------
__global__ __launch_bounds__(BLK, 3) void qc_main_kernel(
    const float* __restrict__ x,
    float*       __restrict__ out,
    int ntok)
{
    const int tid  = threadIdx.x;
    const int tokA = blockIdx.x * (BLK * TPT) + tid;
    const int tokB = tokA + BLK;
    const bool okA = tokA < ntok, okB = tokB < ntok;

    u64 accA[16], accB[16];
    #pragma unroll
    for (int jp = 0; jp < 16; jp++) { accA[jp] = c_blob.b2[jp]; accB[jp] = accA[jp]; }

    u64 one2;
    PACK2(one2, 1.0f, 1.0f);

    const float4* xp4 = reinterpret_cast<const float4*>(x);

    // prefetch x for head 0
    float4 xaN = okA ? xp4[(size_t)tokA * NH + 0] : make_float4(0.f, 0.f, 0.f, 0.f);
    float4 xbN = okB ? xp4[(size_t)tokB * NH + 0] : make_float4(0.f, 0.f, 0.f, 0.f);

    #pragma unroll 1
    for (int h = 0; h < NH; h++) {
        const float4 xa = xaN, xb = xbN;
        if (h + 1 < NH) {
            xaN = okA ? xp4[(size_t)tokA * NH + (h + 1)] : make_float4(0.f, 0.f, 0.f, 0.f);
            xbN = okB ? xp4[(size_t)tokB * NH + (h + 1)] : make_float4(0.f, 0.f, 0.f, 0.f);
        }

        // dup-packed trig basis: Ad[q][0]=(cos,cos), Ad[q][1]=(sin,sin)
        u64 Ad[4][2], Bd[4][2];
        {
            float c, s;
            __sincosf(xa.x, &s, &c); PACK2(Ad[0][0], c, c); PACK2(Ad[0][1], s, s);
            __sincosf(xa.y, &s, &c); PACK2(Ad[1][0], c, c); PACK2(Ad[1][1], s, s);
            __sincosf(xa.z, &s, &c); PACK2(Ad[2][0], c, c); PACK2(Ad[2][1], s, s);
            __sincosf(xa.w, &s, &c); PACK2(Ad[3][0], c, c); PACK2(Ad[3][1], s, s);
            __sincosf(xb.x, &s, &c); PACK2(Bd[0][0], c, c); PACK2(Bd[0][1], s, s);
            __sincosf(xb.y, &s, &c); PACK2(Bd[1][0], c, c); PACK2(Bd[1][1], s, s);
            __sincosf(xb.z, &s, &c); PACK2(Bd[2][0], c, c); PACK2(Bd[2][1], s, s);
            __sincosf(xb.w, &s, &c); PACK2(Bd[3][0], c, c); PACK2(Bd[3][1], s, s);
        }

        // 3-way split accumulators (one set per a-branch) -> 12 indep chains
        u64 evA01[3], evA23[3], evB01[3], evB23[3];
        #pragma unroll
        for (int a = 0; a < 3; a++) {
            evA01[a] = 0ull; evA23[a] = 0ull; evB01[a] = 0ull; evB23[a] = 0ull;
        }

        int term = 0;
        #pragma unroll
        for (int a = 0; a < 3; a++) {
            u64 pA0 = one2, pB0 = one2;
            if (a > 0) { pA0 = Ad[0][a - 1]; pB0 = Bd[0][a - 1]; }
            #pragma unroll
            for (int b = 0; b < 3; b++) {
                u64 pA1, pB1;
                if (b == 0)      { pA1 = pA0;          pB1 = pB0; }
                else if (a == 0) { pA1 = Ad[1][b - 1]; pB1 = Bd[1][b - 1]; }
                else             { MUL2(pA1, pA0, Ad[1][b - 1]);
                                   MUL2(pB1, pB0, Bd[1][b - 1]); }
                #pragma unroll
                for (int c = 0; c < 3; c++) {
                    const bool v2 = (a | b) != 0;
                    u64 pA2, pB2;
                    if (c == 0)      { pA2 = pA1;          pB2 = pB1; }
                    else if (!v2)    { pA2 = Ad[2][c - 1]; pB2 = Bd[2][c - 1]; }
                    else             { MUL2(pA2, pA1, Ad[2][c - 1]);
                                       MUL2(pB2, pB1, Bd[2][c - 1]); }
                    #pragma unroll
                    for (int d = 0; d < 3; d++) {
                        const bool v3 = (a | b | c) != 0;
                        u64 phA, phB;
                        if (d == 0)      { phA = pA2;          phB = pB2; }
                        else if (!v3)    { phA = Ad[3][d - 1]; phB = Bd[3][d - 1]; }
                        else             { MUL2(phA, pA2, Ad[3][d - 1]);
                                           MUL2(phB, pB2, Bd[3][d - 1]); }
                        const ulonglong2 cc = c_blob.C[h * NT3 + term];   // uniform LDC
                        FMAX2(evA01[a], cc.x, phA, evA01[a]);
                        FMAX2(evA23[a], cc.y, phA, evA23[a]);
                        FMAX2(evB01[a], cc.x, phB, evB01[a]);
                        FMAX2(evB23[a], cc.y, phB, evB23[a]);
                        term++;
                    }
                }
            }
        }

        // merge the 3 branch accumulators
        u64 sA01, sA23, sB01, sB23, tmp;
        ADD2(tmp, evA01[0], evA01[1]); ADD2(sA01, tmp, evA01[2]);
        ADD2(tmp, evA23[0], evA23[1]); ADD2(sA23, tmp, evA23[2]);
        ADD2(tmp, evB01[0], evB01[1]); ADD2(sB01, tmp, evB01[2]);
        ADD2(tmp, evB23[0], evB23[1]); ADD2(sB23, tmp, evB23[2]);

        // Fold into j-packed accumulators; W comes from constant (uniform LDC).
        u64 dA[4], dB[4];
        {
            float e0, e1, e2, e3;
            UNPACK2(e0, e1, sA01); UNPACK2(e2, e3, sA23);
            PACK2(dA[0], e0, e0); PACK2(dA[1], e1, e1);
            PACK2(dA[2], e2, e2); PACK2(dA[3], e3, e3);
            UNPACK2(e0, e1, sB01); UNPACK2(e2, e3, sB23);
            PACK2(dB[0], e0, e0); PACK2(dB[1], e1, e1);
            PACK2(dB[2], e2, e2); PACK2(dB[3], e3, e3);
        }
        #pragma unroll
        for (int i = 0; i < 4; i++) {
            const u64 ai = dA[i], bi = dB[i];
            #pragma unroll
            for (int k = 0; k < 8; k++) {
                const ulonglong2 wd = c_blob.Wq[h * 32 + i * 8 + k];      // uniform LDC
                FMAX2(accA[2 * k],     wd.x, ai, accA[2 * k]);
                FMAX2(accA[2 * k + 1], wd.y, ai, accA[2 * k + 1]);
                FMAX2(accB[2 * k],     wd.x, bi, accB[2 * k]);
                FMAX2(accB[2 * k + 1], wd.y, bi, accB[2 * k + 1]);
            }
        }
    }

    if (okA) {
        ulonglong2* op = reinterpret_cast<ulonglong2*>(out + (size_t)tokA * EMB);
        #pragma unroll
        for (int jj = 0; jj < 8; jj++)
            op[jj] = make_ulonglong2(accA[2 * jj], accA[2 * jj + 1]);
    }
    if (okB) {
        ulonglong2* op = reinterpret_cast<ulonglong2*>(out + (size_t)tokB * EMB);
        #pragma unroll
        for (int jj = 0; jj < 8; jj++)
            op[jj] = make_ulonglong2(accB[2 * jj], accB[2 * jj + 1]);
    }
}

// ---------------------------------------------------------------------------
extern "C" void kernel_launch(void* const* d_in, const int* in_sizes, int n_in,
                              void* d_out, int out_size) {
    const float* x      = (const float*)d_in[0];
    const float* params = (const float*)d_in[1];
    const float* W      = (const float*)d_in[2];
    const float* b      = (const float*)d_in[3];
    float* out = (float*)d_out;

    const int ntok = in_sizes[0] / EMB;

    qc_setup_kernel<<<NH, 256>>>(params, W, b);

    // Blob -> __constant__ (device-to-device memcpy node; graph-capturable).
    void *src = nullptr, *dst = nullptr;
    cudaGetSymbolAddress(&src, g_blob);
    cudaGetSymbolAddress(&dst, c_blob);
    cudaMemcpyAsync(dst, src, sizeof(CBlob), cudaMemcpyDeviceToDevice, 0);

    const int tok_per_block = BLK * TPT;
    const int blocks = (ntok + tok_per_block - 1) / tok_per_block;
    qc_main_kernel<<<blocks, BLK>>>(x, out, ntok);
}